// round 1
// baseline (speedup 1.0000x reference)
#include <cuda_runtime.h>
#include <math.h>

// Problem constants
#define DMODEL 1024
#define HEADS  16
#define DH     64
#define SEQ    2048
#define BATCH  2
#define TROWS  (BATCH*SEQ)   // 4096

// Scratch (allocation-free rule: __device__ globals)
__device__ float g_Q[TROWS*DMODEL];
__device__ float g_K[TROWS*DMODEL];
__device__ float g_V[TROWS*DMODEL];
__device__ float g_AO[TROWS*DMODEL];

// ---------------------------------------------------------------------------
// Generic SGEMM: C[M,N] = A[M,K] * B[K,N]; 128x128 block tile, K-step 8,
// 256 threads, 8x8 register microtile per thread. Requires M%128==0,
// N%128==0, K%8==0 (true for all 4 uses here).
// ---------------------------------------------------------------------------
__global__ __launch_bounds__(256) void sgemm_kernel(
    const float* __restrict__ A, const float* __restrict__ B,
    float* __restrict__ C, int M, int N, int K)
{
    __shared__ __align__(16) float As[8][128];
    __shared__ __align__(16) float Bs[8][128];

    const int tid = threadIdx.x;
    const int tx = tid & 15;        // 0..15 -> N microtiles
    const int ty = tid >> 4;        // 0..15 -> M microtiles
    const int m0 = blockIdx.y * 128;
    const int n0 = blockIdx.x * 128;

    // A tile load mapping: one float4 per thread along K, stored transposed
    const int arow = tid >> 1;          // 0..127
    const int acol = (tid & 1) * 4;     // 0 or 4
    // B tile load mapping: one float4 per thread along N
    const int brow = tid >> 5;          // 0..7
    const int bcol = (tid & 31) * 4;    // 0..124

    float acc[8][8];
    #pragma unroll
    for (int i = 0; i < 8; i++)
        #pragma unroll
        for (int j = 0; j < 8; j++) acc[i][j] = 0.f;

    const float* Aptr = A + (size_t)(m0 + arow) * K + acol;
    const float* Bptr = B + (size_t)brow * N + n0 + bcol;

    for (int k0 = 0; k0 < K; k0 += 8) {
        float4 av = *(const float4*)(Aptr + k0);
        float4 bv = *(const float4*)(Bptr + (size_t)k0 * N);
        As[acol + 0][arow] = av.x;
        As[acol + 1][arow] = av.y;
        As[acol + 2][arow] = av.z;
        As[acol + 3][arow] = av.w;
        *(float4*)&Bs[brow][bcol] = bv;
        __syncthreads();

        #pragma unroll
        for (int kk = 0; kk < 8; kk++) {
            float a[8], b[8];
            *(float4*)&a[0] = *(const float4*)&As[kk][ty * 8];
            *(float4*)&a[4] = *(const float4*)&As[kk][ty * 8 + 4];
            *(float4*)&b[0] = *(const float4*)&Bs[kk][tx * 8];
            *(float4*)&b[4] = *(const float4*)&Bs[kk][tx * 8 + 4];
            #pragma unroll
            for (int i = 0; i < 8; i++)
                #pragma unroll
                for (int j = 0; j < 8; j++)
                    acc[i][j] += a[i] * b[j];
        }
        __syncthreads();
    }

    #pragma unroll
    for (int i = 0; i < 8; i++) {
        float* Crow = C + (size_t)(m0 + ty * 8 + i) * N + n0 + tx * 8;
        *(float4*)Crow       = make_float4(acc[i][0], acc[i][1], acc[i][2], acc[i][3]);
        *(float4*)(Crow + 4) = make_float4(acc[i][4], acc[i][5], acc[i][6], acc[i][7]);
    }
}

// ---------------------------------------------------------------------------
// RoPE applied in-place to g_Q and g_K.
// Layout per token row: [h*64 + d], halves at d and d+32 rotate together.
// ---------------------------------------------------------------------------
__global__ void rope_kernel(const float* __restrict__ cosT,
                            const float* __restrict__ sinT)
{
    int idx = blockIdx.x * blockDim.x + threadIdx.x;   // over TROWS*HEADS*32
    if (idx >= TROWS * HEADS * 32) return;
    int d = idx & 31;
    int h = (idx >> 5) & (HEADS - 1);
    int t = idx >> 9;              // token row 0..TROWS-1
    int s = t & (SEQ - 1);         // position within sequence
    float c  = cosT[s * 32 + d];
    float sn = sinT[s * 32 + d];
    int base = t * DMODEL + h * DH;

    float q1 = g_Q[base + d], q2 = g_Q[base + d + 32];
    g_Q[base + d]      = q1 * c - q2 * sn;
    g_Q[base + d + 32] = q2 * c + q1 * sn;

    float k1 = g_K[base + d], k2 = g_K[base + d + 32];
    g_K[base + d]      = k1 * c - k2 * sn;
    g_K[base + d + 32] = k2 * c + k1 * sn;
}

// ---------------------------------------------------------------------------
// Causal flash attention. One CTA per (b, h, 64-row query tile).
// 256 threads as 16x16; each thread owns a 4x4 microtile of the 64x64
// scores and a 4x4 microtile of O (4 rows x 4 of the 64 Dh cols).
// Qt/Kt stored d-major ([d][row]) -> conflict-free float4 reads in the
// scores GEMM. P stored transposed ([key][qrow]) into the Kt buffer,
// V stored natural ([key][d]) -> conflict-free float4 reads in the PV GEMM.
// ---------------------------------------------------------------------------
__global__ __launch_bounds__(256) void attn_kernel()
{
    __shared__ __align__(16) float Qt[64][64];   // [d][r]
    __shared__ __align__(16) float Kt[64][64];   // [d][c]; reused as Pt[j][r]
    __shared__ __align__(16) float Vs[64][64];   // [j][d]

    const int tid = threadIdx.x;
    const int tx = tid & 15;
    const int ty = tid >> 4;
    const int qt = blockIdx.x;           // 0..31
    const int h  = blockIdx.y;
    const int b  = blockIdx.z;
    const int qbase = b * SEQ + qt * 64; // global token row of q tile start

    // Load Q tile transposed: Qt[d][r]
    {
        int row = tid >> 2;            // 0..63
        int d4  = (tid & 3) * 16;      // 16 d-values per thread
        const float* qp = g_Q + (size_t)(qbase + row) * DMODEL + h * DH + d4;
        #pragma unroll
        for (int t4 = 0; t4 < 4; t4++) {
            float4 v = *(const float4*)(qp + t4 * 4);
            Qt[d4 + t4 * 4 + 0][row] = v.x;
            Qt[d4 + t4 * 4 + 1][row] = v.y;
            Qt[d4 + t4 * 4 + 2][row] = v.z;
            Qt[d4 + t4 * 4 + 3][row] = v.w;
        }
    }

    float mrow[4], lrow[4], acc[4][4];
    #pragma unroll
    for (int i = 0; i < 4; i++) {
        mrow[i] = -1e30f; lrow[i] = 0.f;
        #pragma unroll
        for (int j = 0; j < 4; j++) acc[i][j] = 0.f;
    }

    const int r0 = ty * 4;   // score/O rows owned
    const int c0 = tx * 4;   // score cols / O Dh-cols owned
    const float scale = 0.125f;   // Dh^-0.5

    for (int kt = 0; kt <= qt; kt++) {
        const int kbase = b * SEQ + kt * 64;
        __syncthreads();   // previous iteration's Pt/Vs reads complete
        // Load K transposed (Kt[d][c]) and V natural (Vs[j][d])
        {
            int row = tid >> 2;
            int d4  = (tid & 3) * 16;
            const float* kp = g_K + (size_t)(kbase + row) * DMODEL + h * DH + d4;
            const float* vp = g_V + (size_t)(kbase + row) * DMODEL + h * DH + d4;
            #pragma unroll
            for (int t4 = 0; t4 < 4; t4++) {
                float4 v = *(const float4*)(kp + t4 * 4);
                Kt[d4 + t4 * 4 + 0][row] = v.x;
                Kt[d4 + t4 * 4 + 1][row] = v.y;
                Kt[d4 + t4 * 4 + 2][row] = v.z;
                Kt[d4 + t4 * 4 + 3][row] = v.w;
                float4 w = *(const float4*)(vp + t4 * 4);
                *(float4*)&Vs[row][d4 + t4 * 4] = w;
            }
        }
        __syncthreads();

        // Scores: s[i][j] = Q[r0+i] . K[c0+j]
        float sreg[4][4];
        #pragma unroll
        for (int i = 0; i < 4; i++)
            #pragma unroll
            for (int j = 0; j < 4; j++) sreg[i][j] = 0.f;

        #pragma unroll 8
        for (int d = 0; d < 64; d++) {
            float4 qv = *(const float4*)&Qt[d][r0];
            float4 kv = *(const float4*)&Kt[d][c0];
            float qa[4] = {qv.x, qv.y, qv.z, qv.w};
            float ka[4] = {kv.x, kv.y, kv.z, kv.w};
            #pragma unroll
            for (int i = 0; i < 4; i++)
                #pragma unroll
                for (int j = 0; j < 4; j++)
                    sreg[i][j] += qa[i] * ka[j];
        }

        const bool diag = (kt == qt);
        #pragma unroll
        for (int i = 0; i < 4; i++)
            #pragma unroll
            for (int j = 0; j < 4; j++) {
                sreg[i][j] *= scale;
                if (diag && (c0 + j) > (r0 + i)) sreg[i][j] = -1e30f;
            }

        // Online softmax update (row stats across the 16 tx lanes)
        #pragma unroll
        for (int i = 0; i < 4; i++) {
            float mx = fmaxf(fmaxf(sreg[i][0], sreg[i][1]),
                             fmaxf(sreg[i][2], sreg[i][3]));
            #pragma unroll
            for (int off = 8; off; off >>= 1)
                mx = fmaxf(mx, __shfl_xor_sync(0xffffffffu, mx, off));
            float mnew = fmaxf(mrow[i], mx);
            float alpha = __expf(mrow[i] - mnew);
            mrow[i] = mnew;
            float sum = 0.f;
            #pragma unroll
            for (int j = 0; j < 4; j++) {
                sreg[i][j] = __expf(sreg[i][j] - mnew);
                sum += sreg[i][j];
            }
            #pragma unroll
            for (int off = 8; off; off >>= 1)
                sum += __shfl_xor_sync(0xffffffffu, sum, off);
            lrow[i] = lrow[i] * alpha + sum;
            #pragma unroll
            for (int j = 0; j < 4; j++) acc[i][j] *= alpha;
        }

        __syncthreads();   // all scores reads of Kt done
        // Store P transposed into Kt: Pt[j][r]
        #pragma unroll
        for (int i = 0; i < 4; i++)
            #pragma unroll
            for (int j = 0; j < 4; j++)
                Kt[c0 + j][r0 + i] = sreg[i][j];
        __syncthreads();

        // O[r][c] += sum_j Pt[j][r] * Vs[j][c]
        #pragma unroll 8
        for (int j = 0; j < 64; j++) {
            float4 pv = *(const float4*)&Kt[j][r0];
            float4 vv = *(const float4*)&Vs[j][c0];
            float pa[4] = {pv.x, pv.y, pv.z, pv.w};
            float va[4] = {vv.x, vv.y, vv.z, vv.w};
            #pragma unroll
            for (int i = 0; i < 4; i++)
                #pragma unroll
                for (int jj = 0; jj < 4; jj++)
                    acc[i][jj] += pa[i] * va[jj];
        }
    }

    // Normalize and write O to g_AO (layout [token][h*64 + d])
    #pragma unroll
    for (int i = 0; i < 4; i++) {
        float inv = 1.f / lrow[i];
        float4 o = make_float4(acc[i][0] * inv, acc[i][1] * inv,
                               acc[i][2] * inv, acc[i][3] * inv);
        *(float4*)(g_AO + (size_t)(qbase + r0 + i) * DMODEL + h * DH + c0) = o;
    }
}

// ---------------------------------------------------------------------------
// kernel_launch
// Inputs: 0 hidden_states [2,2048,1024] f32, 1 cos [2048,32], 2 sin [2048,32],
//         3 attention_mask (causal, re-derived internally), 4 Wq, 5 Wk, 6 Wv,
//         7 Wo (all [1024,1024] f32). Output: [2,2048,1024] f32.
// ---------------------------------------------------------------------------
extern "C" void kernel_launch(void* const* d_in, const int* in_sizes, int n_in,
                              void* d_out, int out_size)
{
    const float* X    = (const float*)d_in[0];
    const float* cosT = (const float*)d_in[1];
    const float* sinT = (const float*)d_in[2];
    const float* Wq   = (const float*)d_in[4];
    const float* Wk   = (const float*)d_in[5];
    const float* Wv   = (const float*)d_in[6];
    const float* Wo   = (const float*)d_in[7];
    float* out = (float*)d_out;

    float *pQ, *pK, *pV, *pAO;
    cudaGetSymbolAddress((void**)&pQ,  g_Q);
    cudaGetSymbolAddress((void**)&pK,  g_K);
    cudaGetSymbolAddress((void**)&pV,  g_V);
    cudaGetSymbolAddress((void**)&pAO, g_AO);

    dim3 gemm_grid(DMODEL / 128, TROWS / 128);   // (8, 32)
    sgemm_kernel<<<gemm_grid, 256>>>(X, Wq, pQ, TROWS, DMODEL, DMODEL);
    sgemm_kernel<<<gemm_grid, 256>>>(X, Wk, pK, TROWS, DMODEL, DMODEL);
    sgemm_kernel<<<gemm_grid, 256>>>(X, Wv, pV, TROWS, DMODEL, DMODEL);

    int rope_total = TROWS * HEADS * 32;
    rope_kernel<<<(rope_total + 255) / 256, 256>>>(cosT, sinT);

    dim3 attn_grid(SEQ / 64, HEADS, BATCH);      // (32, 16, 2)
    attn_kernel<<<attn_grid, 256>>>();

    sgemm_kernel<<<gemm_grid, 256>>>(pAO, Wo, out, TROWS, DMODEL, DMODEL);

    (void)in_sizes; (void)n_in; (void)out_size;
}

// round 4
// speedup vs baseline: 1.4400x; 1.4400x over previous
#include <cuda_runtime.h>
#include <cstdint>
#include <math.h>

// Problem constants
#define DMODEL 1024
#define HEADS  16
#define DH     64
#define SEQ    2048
#define BATCH  2
#define TROWS  (BATCH*SEQ)   // 4096

// Scratch (allocation-free rule: __device__ globals)
__device__ float g_Q[TROWS*DMODEL];
__device__ float g_K[TROWS*DMODEL];
__device__ float g_V[TROWS*DMODEL];
__device__ float g_AO[TROWS*DMODEL];

// ---------------------------------------------------------------------------
// Helpers
// ---------------------------------------------------------------------------
__device__ __forceinline__ uint32_t smem_u32(const void* p) {
    uint32_t a;
    asm("{ .reg .u64 t; cvta.to.shared.u64 t, %1; cvt.u32.u64 %0, t; }"
        : "=r"(a) : "l"(p));
    return a;
}
__device__ __forceinline__ uint32_t f2tf32(float f) {
    uint32_t r;
    asm("cvt.rna.tf32.f32 %0, %1;" : "=r"(r) : "f"(f));
    return r;
}
__device__ __forceinline__ void mma_tf32(float* d, const uint32_t* a,
                                         const uint32_t* b) {
    asm volatile(
        "mma.sync.aligned.m16n8k8.row.col.f32.tf32.tf32.f32 "
        "{%0,%1,%2,%3}, {%4,%5,%6,%7}, {%8,%9}, {%0,%1,%2,%3};"
        : "+f"(d[0]), "+f"(d[1]), "+f"(d[2]), "+f"(d[3])
        : "r"(a[0]), "r"(a[1]), "r"(a[2]), "r"(a[3]), "r"(b[0]), "r"(b[1]));
}

// ---------------------------------------------------------------------------
// tf32 mma.sync GEMM: C[M,N] = A[M,K]*B[K,N], fp32 in/out.
// CTA 128x128, 8 warps, warp tile 64x32, K-chunk 32, double-buffered SMEM.
// SMEM holds mma fragment records:
//   A record (16B/lane): {a0,a1,a2,a3} of block (KS,MB), word off ((KS*8+MB)*128 + lane*4)
//   B record ( 8B/lane): {b0,b1}      of block (KS,NB), word off ((KS*16+NB)*64 + lane*2)
// Requires M%128==0, N%128==0, K%32==0.
// ---------------------------------------------------------------------------
#define GEMM_DSMEM 65536

__global__ __launch_bounds__(256) void tgemm_kernel(
    const float* __restrict__ A, const float* __restrict__ B,
    float* __restrict__ C, int M, int N, int K)
{
    extern __shared__ __align__(16) char dyn[];
    const uint32_t base = smem_u32(dyn);
    // byte offsets: A buffers 0 / 16384, B buffers 32768 / 49152

    const int tid  = threadIdx.x;
    const int lane = tid & 31;
    const int wid  = tid >> 5;
    const int m0 = blockIdx.y * 128;
    const int n0 = blockIdx.x * 128;

    // ---- producer geometry ----
    const int pr = lane >> 2;   // 0..7
    const int pc = lane & 3;    // 0..3
    const int MBa = wid;        // owns A m-block wid (rows MBa*16 .. +15)
    const int NBb = wid;        // owns B n-blocks wid and wid+8

    const float* pA0 = A + (size_t)(m0 + MBa * 16 + pr) * K + pc;
    const float* pA1 = pA0 + (size_t)8 * K;

    float areg[16], breg[16];

    #define LDG_CHUNK(k0)                                                   \
    {                                                                       \
        _Pragma("unroll")                                                   \
        for (int q = 0; q < 4; q++) {                                       \
            int kq = (k0) + q * 8;                                          \
            areg[q * 4 + 0] = pA0[kq];                                      \
            areg[q * 4 + 1] = pA1[kq];                                      \
            areg[q * 4 + 2] = pA0[kq + 4];                                  \
            areg[q * 4 + 3] = pA1[kq + 4];                                  \
        }                                                                   \
        _Pragma("unroll")                                                   \
        for (int h = 0; h < 2; h++)                                         \
            _Pragma("unroll")                                               \
            for (int q = 0; q < 4; q++) {                                   \
                int k = (k0) + q * 8 + pc;                                  \
                int n = n0 + (NBb + 8 * h) * 8 + pr;                        \
                breg[(h * 4 + q) * 2 + 0] = B[(size_t)k * N + n];           \
                breg[(h * 4 + q) * 2 + 1] = B[(size_t)(k + 4) * N + n];     \
            }                                                               \
    }

    #define STS_CHUNK(bi)                                                   \
    {                                                                       \
        uint32_t ba = base + (uint32_t)(bi) * 16384u;                       \
        uint32_t bb = base + 32768u + (uint32_t)(bi) * 16384u;              \
        _Pragma("unroll")                                                   \
        for (int q = 0; q < 4; q++) {                                       \
            uint32_t off = ba + (uint32_t)(((q * 8 + MBa) * 128 + lane * 4) * 4); \
            uint32_t x = f2tf32(areg[q * 4 + 0]);                           \
            uint32_t y = f2tf32(areg[q * 4 + 1]);                           \
            uint32_t z = f2tf32(areg[q * 4 + 2]);                           \
            uint32_t w = f2tf32(areg[q * 4 + 3]);                           \
            asm volatile("st.shared.v4.b32 [%0], {%1,%2,%3,%4};"            \
                         :: "r"(off), "r"(x), "r"(y), "r"(z), "r"(w) : "memory"); \
        }                                                                   \
        _Pragma("unroll")                                                   \
        for (int h = 0; h < 2; h++)                                         \
            _Pragma("unroll")                                               \
            for (int q = 0; q < 4; q++) {                                   \
                uint32_t off = bb + (uint32_t)(((q * 16 + NBb + 8 * h) * 64 + lane * 2) * 4); \
                uint32_t x = f2tf32(breg[(h * 4 + q) * 2 + 0]);             \
                uint32_t y = f2tf32(breg[(h * 4 + q) * 2 + 1]);             \
                asm volatile("st.shared.v2.b32 [%0], {%1,%2};"              \
                             :: "r"(off), "r"(x), "r"(y) : "memory");       \
            }                                                               \
    }

    // ---- consumer geometry ----
    const int wmb = (wid & 1) * 4;   // first MB of this warp (4 blocks)
    const int wnb = (wid >> 1) * 4;  // first NB of this warp (4 blocks)

    float acc[4][4][4];
    #pragma unroll
    for (int i = 0; i < 4; i++)
        #pragma unroll
        for (int j = 0; j < 4; j++)
            #pragma unroll
            for (int r = 0; r < 4; r++) acc[i][j][r] = 0.f;

    #define MMA_CHUNK(bi)                                                   \
    {                                                                       \
        uint32_t ba = base + (uint32_t)(bi) * 16384u;                       \
        uint32_t bb = base + 32768u + (uint32_t)(bi) * 16384u;              \
        _Pragma("unroll")                                                   \
        for (int KS = 0; KS < 4; KS++) {                                    \
            uint32_t af[4][4], bf[4][2];                                    \
            _Pragma("unroll")                                               \
            for (int mb = 0; mb < 4; mb++) {                                \
                uint32_t off = ba + (uint32_t)(((KS * 8 + wmb + mb) * 128 + lane * 4) * 4); \
                asm volatile("ld.shared.v4.b32 {%0,%1,%2,%3}, [%4];"        \
                             : "=r"(af[mb][0]), "=r"(af[mb][1]),            \
                               "=r"(af[mb][2]), "=r"(af[mb][3])             \
                             : "r"(off));                                   \
            }                                                               \
            _Pragma("unroll")                                               \
            for (int nb = 0; nb < 4; nb++) {                                \
                uint32_t off = bb + (uint32_t)(((KS * 16 + wnb + nb) * 64 + lane * 2) * 4); \
                asm volatile("ld.shared.v2.b32 {%0,%1}, [%2];"              \
                             : "=r"(bf[nb][0]), "=r"(bf[nb][1]) : "r"(off));\
            }                                                               \
            _Pragma("unroll")                                               \
            for (int mb = 0; mb < 4; mb++)                                  \
                _Pragma("unroll")                                           \
                for (int nb = 0; nb < 4; nb++)                              \
                    mma_tf32(acc[mb][nb], af[mb], bf[nb]);                  \
        }                                                                   \
    }

    const int nch = K / 32;

    LDG_CHUNK(0);
    STS_CHUNK(0);
    __syncthreads();

    for (int c = 0; c < nch; c++) {
        const int bi = c & 1;
        if (c + 1 < nch) LDG_CHUNK((c + 1) * 32);
        MMA_CHUNK(bi);
        __syncthreads();
        if (c + 1 < nch) STS_CHUNK(1 - bi);
        __syncthreads();
    }

    // ---- epilogue ----
    #pragma unroll
    for (int mb = 0; mb < 4; mb++) {
        const int row = m0 + (wmb + mb) * 16 + (lane >> 2);
        #pragma unroll
        for (int nb = 0; nb < 4; nb++) {
            const int col = n0 + (wnb + nb) * 8 + 2 * (lane & 3);
            float2 v0 = make_float2(acc[mb][nb][0], acc[mb][nb][1]);
            float2 v1 = make_float2(acc[mb][nb][2], acc[mb][nb][3]);
            *(float2*)&C[(size_t)row * N + col]       = v0;
            *(float2*)&C[(size_t)(row + 8) * N + col] = v1;
        }
    }
    #undef LDG_CHUNK
    #undef STS_CHUNK
    #undef MMA_CHUNK
}

// ---------------------------------------------------------------------------
// RoPE applied in-place to g_Q and g_K.
// ---------------------------------------------------------------------------
__global__ void rope_kernel(const float* __restrict__ cosT,
                            const float* __restrict__ sinT)
{
    int idx = blockIdx.x * blockDim.x + threadIdx.x;   // over TROWS*HEADS*32
    if (idx >= TROWS * HEADS * 32) return;
    int d = idx & 31;
    int h = (idx >> 5) & (HEADS - 1);
    int t = idx >> 9;
    int s = t & (SEQ - 1);
    float c  = cosT[s * 32 + d];
    float sn = sinT[s * 32 + d];
    int base = t * DMODEL + h * DH;

    float q1 = g_Q[base + d], q2 = g_Q[base + d + 32];
    g_Q[base + d]      = q1 * c - q2 * sn;
    g_Q[base + d + 32] = q2 * c + q1 * sn;

    float k1 = g_K[base + d], k2 = g_K[base + d + 32];
    g_K[base + d]      = k1 * c - k2 * sn;
    g_K[base + d + 32] = k2 * c + k1 * sn;
}

// ---------------------------------------------------------------------------
// Causal flash attention (fp32). One CTA per (b, h, 64-row q tile);
// 256 threads as 16x16, 4x4 microtiles.
// ---------------------------------------------------------------------------
__global__ __launch_bounds__(256) void attn_kernel()
{
    __shared__ __align__(16) float Qt[64][64];   // [d][r]
    __shared__ __align__(16) float Kt[64][64];   // [d][c]; reused as Pt[j][r]
    __shared__ __align__(16) float Vs[64][64];   // [j][d]

    const int tid = threadIdx.x;
    const int tx = tid & 15;
    const int ty = tid >> 4;
    const int qt = blockIdx.x;
    const int h  = blockIdx.y;
    const int b  = blockIdx.z;
    const int qbase = b * SEQ + qt * 64;

    {
        int row = tid >> 2;
        int d4  = (tid & 3) * 16;
        const float* qp = g_Q + (size_t)(qbase + row) * DMODEL + h * DH + d4;
        #pragma unroll
        for (int t4 = 0; t4 < 4; t4++) {
            float4 v = *(const float4*)(qp + t4 * 4);
            Qt[d4 + t4 * 4 + 0][row] = v.x;
            Qt[d4 + t4 * 4 + 1][row] = v.y;
            Qt[d4 + t4 * 4 + 2][row] = v.z;
            Qt[d4 + t4 * 4 + 3][row] = v.w;
        }
    }

    float mrow[4], lrow[4], acc[4][4];
    #pragma unroll
    for (int i = 0; i < 4; i++) {
        mrow[i] = -1e30f; lrow[i] = 0.f;
        #pragma unroll
        for (int j = 0; j < 4; j++) acc[i][j] = 0.f;
    }

    const int r0 = ty * 4;
    const int c0 = tx * 4;
    const float scale = 0.125f;

    for (int kt = 0; kt <= qt; kt++) {
        const int kbase = b * SEQ + kt * 64;
        __syncthreads();
        {
            int row = tid >> 2;
            int d4  = (tid & 3) * 16;
            const float* kp = g_K + (size_t)(kbase + row) * DMODEL + h * DH + d4;
            const float* vp = g_V + (size_t)(kbase + row) * DMODEL + h * DH + d4;
            #pragma unroll
            for (int t4 = 0; t4 < 4; t4++) {
                float4 v = *(const float4*)(kp + t4 * 4);
                Kt[d4 + t4 * 4 + 0][row] = v.x;
                Kt[d4 + t4 * 4 + 1][row] = v.y;
                Kt[d4 + t4 * 4 + 2][row] = v.z;
                Kt[d4 + t4 * 4 + 3][row] = v.w;
                float4 w = *(const float4*)(vp + t4 * 4);
                *(float4*)&Vs[row][d4 + t4 * 4] = w;
            }
        }
        __syncthreads();

        float sreg[4][4];
        #pragma unroll
        for (int i = 0; i < 4; i++)
            #pragma unroll
            for (int j = 0; j < 4; j++) sreg[i][j] = 0.f;

        #pragma unroll 8
        for (int d = 0; d < 64; d++) {
            float4 qv = *(const float4*)&Qt[d][r0];
            float4 kv = *(const float4*)&Kt[d][c0];
            float qa[4] = {qv.x, qv.y, qv.z, qv.w};
            float ka[4] = {kv.x, kv.y, kv.z, kv.w};
            #pragma unroll
            for (int i = 0; i < 4; i++)
                #pragma unroll
                for (int j = 0; j < 4; j++)
                    sreg[i][j] += qa[i] * ka[j];
        }

        const bool diag = (kt == qt);
        #pragma unroll
        for (int i = 0; i < 4; i++)
            #pragma unroll
            for (int j = 0; j < 4; j++) {
                sreg[i][j] *= scale;
                if (diag && (c0 + j) > (r0 + i)) sreg[i][j] = -1e30f;
            }

        #pragma unroll
        for (int i = 0; i < 4; i++) {
            float mx = fmaxf(fmaxf(sreg[i][0], sreg[i][1]),
                             fmaxf(sreg[i][2], sreg[i][3]));
            #pragma unroll
            for (int off = 8; off; off >>= 1)
                mx = fmaxf(mx, __shfl_xor_sync(0xffffffffu, mx, off));
            float mnew = fmaxf(mrow[i], mx);
            float alpha = __expf(mrow[i] - mnew);
            mrow[i] = mnew;
            float sum = 0.f;
            #pragma unroll
            for (int j = 0; j < 4; j++) {
                sreg[i][j] = __expf(sreg[i][j] - mnew);
                sum += sreg[i][j];
            }
            #pragma unroll
            for (int off = 8; off; off >>= 1)
                sum += __shfl_xor_sync(0xffffffffu, sum, off);
            lrow[i] = lrow[i] * alpha + sum;
            #pragma unroll
            for (int j = 0; j < 4; j++) acc[i][j] *= alpha;
        }

        __syncthreads();
        #pragma unroll
        for (int i = 0; i < 4; i++)
            #pragma unroll
            for (int j = 0; j < 4; j++)
                Kt[c0 + j][r0 + i] = sreg[i][j];
        __syncthreads();

        #pragma unroll 8
        for (int j = 0; j < 64; j++) {
            float4 pv = *(const float4*)&Kt[j][r0];
            float4 vv = *(const float4*)&Vs[j][c0];
            float pa[4] = {pv.x, pv.y, pv.z, pv.w};
            float va[4] = {vv.x, vv.y, vv.z, vv.w};
            #pragma unroll
            for (int i = 0; i < 4; i++)
                #pragma unroll
                for (int jj = 0; jj < 4; jj++)
                    acc[i][jj] += pa[i] * va[jj];
        }
    }

    #pragma unroll
    for (int i = 0; i < 4; i++) {
        float inv = 1.f / lrow[i];
        float4 o = make_float4(acc[i][0] * inv, acc[i][1] * inv,
                               acc[i][2] * inv, acc[i][3] * inv);
        *(float4*)(g_AO + (size_t)(qbase + r0 + i) * DMODEL + h * DH + c0) = o;
    }
}

// ---------------------------------------------------------------------------
// kernel_launch
// ---------------------------------------------------------------------------
extern "C" void kernel_launch(void* const* d_in, const int* in_sizes, int n_in,
                              void* d_out, int out_size)
{
    const float* X    = (const float*)d_in[0];
    const float* cosT = (const float*)d_in[1];
    const float* sinT = (const float*)d_in[2];
    const float* Wq   = (const float*)d_in[4];
    const float* Wk   = (const float*)d_in[5];
    const float* Wv   = (const float*)d_in[6];
    const float* Wo   = (const float*)d_in[7];
    float* out = (float*)d_out;

    float *pQ, *pK, *pV, *pAO;
    cudaGetSymbolAddress((void**)&pQ,  g_Q);
    cudaGetSymbolAddress((void**)&pK,  g_K);
    cudaGetSymbolAddress((void**)&pV,  g_V);
    cudaGetSymbolAddress((void**)&pAO, g_AO);

    cudaFuncSetAttribute(tgemm_kernel,
                         cudaFuncAttributeMaxDynamicSharedMemorySize, GEMM_DSMEM);

    dim3 gemm_grid(DMODEL / 128, TROWS / 128);   // (8, 32)
    tgemm_kernel<<<gemm_grid, 256, GEMM_DSMEM>>>(X, Wq, pQ, TROWS, DMODEL, DMODEL);
    tgemm_kernel<<<gemm_grid, 256, GEMM_DSMEM>>>(X, Wk, pK, TROWS, DMODEL, DMODEL);
    tgemm_kernel<<<gemm_grid, 256, GEMM_DSMEM>>>(X, Wv, pV, TROWS, DMODEL, DMODEL);

    int rope_total = TROWS * HEADS * 32;
    rope_kernel<<<(rope_total + 255) / 256, 256>>>(cosT, sinT);

    dim3 attn_grid(SEQ / 64, HEADS, BATCH);      // (32, 16, 2)
    attn_kernel<<<attn_grid, 256>>>();

    tgemm_kernel<<<gemm_grid, 256, GEMM_DSMEM>>>(pAO, Wo, out, TROWS, DMODEL, DMODEL);

    (void)in_sizes; (void)n_in; (void)out_size;
}

// round 5
// speedup vs baseline: 2.0761x; 1.4418x over previous
#include <cuda_runtime.h>
#include <cstdint>
#include <math.h>

// Problem constants
#define DMODEL 1024
#define HEADS  16
#define DH     64
#define SEQ    2048
#define BATCH  2
#define TROWS  (BATCH*SEQ)   // 4096

// Scratch (allocation-free rule: __device__ globals)
__device__ float g_Q[TROWS*DMODEL];
__device__ float g_K[TROWS*DMODEL];
__device__ float g_V[TROWS*DMODEL];
__device__ float g_AO[TROWS*DMODEL];

// ---------------------------------------------------------------------------
// Helpers
// ---------------------------------------------------------------------------
__device__ __forceinline__ uint32_t smem_u32(const void* p) {
    uint32_t a;
    asm("{ .reg .u64 t; cvta.to.shared.u64 t, %1; cvt.u32.u64 %0, t; }"
        : "=r"(a) : "l"(p));
    return a;
}
__device__ __forceinline__ uint32_t f2tf32(float f) {
    uint32_t r;
    asm("cvt.rna.tf32.f32 %0, %1;" : "=r"(r) : "f"(f));
    return r;
}
__device__ __forceinline__ void mma_tf32(float* d, const uint32_t* a,
                                         const uint32_t* b) {
    asm volatile(
        "mma.sync.aligned.m16n8k8.row.col.f32.tf32.tf32.f32 "
        "{%0,%1,%2,%3}, {%4,%5,%6,%7}, {%8,%9}, {%0,%1,%2,%3};"
        : "+f"(d[0]), "+f"(d[1]), "+f"(d[2]), "+f"(d[3])
        : "r"(a[0]), "r"(a[1]), "r"(a[2]), "r"(a[3]), "r"(b[0]), "r"(b[1]));
}

// ---------------------------------------------------------------------------
// tf32 mma.sync GEMM: C[M,N] = A[M,K]*B[K,N], fp32 in/out.  (unchanged R4)
// CTA 128x128, 8 warps, warp tile 64x32, K-chunk 32, double-buffered SMEM.
// ---------------------------------------------------------------------------
#define GEMM_DSMEM 65536

__global__ __launch_bounds__(256) void tgemm_kernel(
    const float* __restrict__ A, const float* __restrict__ B,
    float* __restrict__ C, int M, int N, int K)
{
    extern __shared__ __align__(16) char dyn[];
    const uint32_t base = smem_u32(dyn);

    const int tid  = threadIdx.x;
    const int lane = tid & 31;
    const int wid  = tid >> 5;
    const int m0 = blockIdx.y * 128;
    const int n0 = blockIdx.x * 128;

    const int pr = lane >> 2;
    const int pc = lane & 3;
    const int MBa = wid;
    const int NBb = wid;

    const float* pA0 = A + (size_t)(m0 + MBa * 16 + pr) * K + pc;
    const float* pA1 = pA0 + (size_t)8 * K;

    float areg[16], breg[16];

    #define LDG_CHUNK(k0)                                                   \
    {                                                                       \
        _Pragma("unroll")                                                   \
        for (int q = 0; q < 4; q++) {                                       \
            int kq = (k0) + q * 8;                                          \
            areg[q * 4 + 0] = pA0[kq];                                      \
            areg[q * 4 + 1] = pA1[kq];                                      \
            areg[q * 4 + 2] = pA0[kq + 4];                                  \
            areg[q * 4 + 3] = pA1[kq + 4];                                  \
        }                                                                   \
        _Pragma("unroll")                                                   \
        for (int h = 0; h < 2; h++)                                         \
            _Pragma("unroll")                                               \
            for (int q = 0; q < 4; q++) {                                   \
                int k = (k0) + q * 8 + pc;                                  \
                int n = n0 + (NBb + 8 * h) * 8 + pr;                        \
                breg[(h * 4 + q) * 2 + 0] = B[(size_t)k * N + n];           \
                breg[(h * 4 + q) * 2 + 1] = B[(size_t)(k + 4) * N + n];     \
            }                                                               \
    }

    #define STS_CHUNK(bi)                                                   \
    {                                                                       \
        uint32_t ba = base + (uint32_t)(bi) * 16384u;                       \
        uint32_t bb = base + 32768u + (uint32_t)(bi) * 16384u;              \
        _Pragma("unroll")                                                   \
        for (int q = 0; q < 4; q++) {                                       \
            uint32_t off = ba + (uint32_t)(((q * 8 + MBa) * 128 + lane * 4) * 4); \
            uint32_t x = f2tf32(areg[q * 4 + 0]);                           \
            uint32_t y = f2tf32(areg[q * 4 + 1]);                           \
            uint32_t z = f2tf32(areg[q * 4 + 2]);                           \
            uint32_t w = f2tf32(areg[q * 4 + 3]);                           \
            asm volatile("st.shared.v4.b32 [%0], {%1,%2,%3,%4};"            \
                         :: "r"(off), "r"(x), "r"(y), "r"(z), "r"(w) : "memory"); \
        }                                                                   \
        _Pragma("unroll")                                                   \
        for (int h = 0; h < 2; h++)                                         \
            _Pragma("unroll")                                               \
            for (int q = 0; q < 4; q++) {                                   \
                uint32_t off = bb + (uint32_t)(((q * 16 + NBb + 8 * h) * 64 + lane * 2) * 4); \
                uint32_t x = f2tf32(breg[(h * 4 + q) * 2 + 0]);             \
                uint32_t y = f2tf32(breg[(h * 4 + q) * 2 + 1]);             \
                asm volatile("st.shared.v2.b32 [%0], {%1,%2};"              \
                             :: "r"(off), "r"(x), "r"(y) : "memory");       \
            }                                                               \
    }

    const int wmb = (wid & 1) * 4;
    const int wnb = (wid >> 1) * 4;

    float acc[4][4][4];
    #pragma unroll
    for (int i = 0; i < 4; i++)
        #pragma unroll
        for (int j = 0; j < 4; j++)
            #pragma unroll
            for (int r = 0; r < 4; r++) acc[i][j][r] = 0.f;

    #define MMA_CHUNK(bi)                                                   \
    {                                                                       \
        uint32_t ba = base + (uint32_t)(bi) * 16384u;                       \
        uint32_t bb = base + 32768u + (uint32_t)(bi) * 16384u;              \
        _Pragma("unroll")                                                   \
        for (int KS = 0; KS < 4; KS++) {                                    \
            uint32_t af[4][4], bf[4][2];                                    \
            _Pragma("unroll")                                               \
            for (int mb = 0; mb < 4; mb++) {                                \
                uint32_t off = ba + (uint32_t)(((KS * 8 + wmb + mb) * 128 + lane * 4) * 4); \
                asm volatile("ld.shared.v4.b32 {%0,%1,%2,%3}, [%4];"        \
                             : "=r"(af[mb][0]), "=r"(af[mb][1]),            \
                               "=r"(af[mb][2]), "=r"(af[mb][3])             \
                             : "r"(off));                                   \
            }                                                               \
            _Pragma("unroll")                                               \
            for (int nb = 0; nb < 4; nb++) {                                \
                uint32_t off = bb + (uint32_t)(((KS * 16 + wnb + nb) * 64 + lane * 2) * 4); \
                asm volatile("ld.shared.v2.b32 {%0,%1}, [%2];"              \
                             : "=r"(bf[nb][0]), "=r"(bf[nb][1]) : "r"(off));\
            }                                                               \
            _Pragma("unroll")                                               \
            for (int mb = 0; mb < 4; mb++)                                  \
                _Pragma("unroll")                                           \
                for (int nb = 0; nb < 4; nb++)                              \
                    mma_tf32(acc[mb][nb], af[mb], bf[nb]);                  \
        }                                                                   \
    }

    const int nch = K / 32;

    LDG_CHUNK(0);
    STS_CHUNK(0);
    __syncthreads();

    for (int c = 0; c < nch; c++) {
        const int bi = c & 1;
        if (c + 1 < nch) LDG_CHUNK((c + 1) * 32);
        MMA_CHUNK(bi);
        __syncthreads();
        if (c + 1 < nch) STS_CHUNK(1 - bi);
        __syncthreads();
    }

    #pragma unroll
    for (int mb = 0; mb < 4; mb++) {
        const int row = m0 + (wmb + mb) * 16 + (lane >> 2);
        #pragma unroll
        for (int nb = 0; nb < 4; nb++) {
            const int col = n0 + (wnb + nb) * 8 + 2 * (lane & 3);
            float2 v0 = make_float2(acc[mb][nb][0], acc[mb][nb][1]);
            float2 v1 = make_float2(acc[mb][nb][2], acc[mb][nb][3]);
            *(float2*)&C[(size_t)row * N + col]       = v0;
            *(float2*)&C[(size_t)(row + 8) * N + col] = v1;
        }
    }
    #undef LDG_CHUNK
    #undef STS_CHUNK
    #undef MMA_CHUNK
}

// ---------------------------------------------------------------------------
// RoPE applied in-place to g_Q and g_K.
// ---------------------------------------------------------------------------
__global__ void rope_kernel(const float* __restrict__ cosT,
                            const float* __restrict__ sinT)
{
    int idx = blockIdx.x * blockDim.x + threadIdx.x;   // over TROWS*HEADS*32
    if (idx >= TROWS * HEADS * 32) return;
    int d = idx & 31;
    int h = (idx >> 5) & (HEADS - 1);
    int t = idx >> 9;
    int s = t & (SEQ - 1);
    float c  = cosT[s * 32 + d];
    float sn = sinT[s * 32 + d];
    int base = t * DMODEL + h * DH;

    float q1 = g_Q[base + d], q2 = g_Q[base + d + 32];
    g_Q[base + d]      = q1 * c - q2 * sn;
    g_Q[base + d + 32] = q2 * c + q1 * sn;

    float k1 = g_K[base + d], k2 = g_K[base + d + 32];
    g_K[base + d]      = k1 * c - k2 * sn;
    g_K[base + d + 32] = k2 * c + k1 * sn;
}

// ---------------------------------------------------------------------------
// Tensor-core causal flash attention.
// CTA: 128 threads (4 warps), 64-query tile; warp w owns rows [w*16, w*16+16).
// Key tiles of 64. S = Q*K^T via 3xTF32 (hi/lo split, 3 MMAs) for accuracy;
// P*V via single tf32. Q kept as persistent register fragments; K(hi/lo) and
// V staged in SMEM as mma B-fragment records; P routed through padded
// per-warp SMEM (pitch 68 -> conflict-free A-fragment reads).
// SMEM map (bytes): Khi 0..16K, Klo 16K..32K, V 32K..48K, P 48K + w*4352.
// ---------------------------------------------------------------------------
#define ATT_DSMEM (49152 + 4*4352)   // 66560

__global__ __launch_bounds__(128) void attn_kernel()
{
    extern __shared__ __align__(16) char dynA[];
    const uint32_t Khi = smem_u32(dynA);
    const uint32_t Klo = Khi + 16384u;
    const uint32_t Vsm = Khi + 32768u;

    const int tid  = threadIdx.x;
    const int lane = tid & 31;
    const int w    = tid >> 5;
    const uint32_t Pb = Khi + 49152u + (uint32_t)w * 4352u;
    const int gid = lane >> 2;    // group id (row within 8-block)
    const int tg  = lane & 3;     // thread in group

    const int qt = (SEQ / 64 - 1) - blockIdx.x;   // heavy tiles first
    const int h  = blockIdx.y;
    const int b  = blockIdx.z;
    const int qbase = b * SEQ + qt * 64;

    // ---- persistent Q fragments (hi/lo split) ----
    uint32_t qhi[8][4], qlo[8][4];
    {
        const float* qp = g_Q + (size_t)(qbase + w * 16) * DMODEL + h * DH;
        #pragma unroll
        for (int kb = 0; kb < 8; kb++) {
            float v[4];
            v[0] = qp[(size_t)gid       * DMODEL + kb * 8 + tg];
            v[1] = qp[(size_t)(gid + 8) * DMODEL + kb * 8 + tg];
            v[2] = qp[(size_t)gid       * DMODEL + kb * 8 + tg + 4];
            v[3] = qp[(size_t)(gid + 8) * DMODEL + kb * 8 + tg + 4];
            #pragma unroll
            for (int i = 0; i < 4; i++) {
                qhi[kb][i] = f2tf32(v[i]);
                qlo[kb][i] = f2tf32(v[i] - __uint_as_float(qhi[kb][i]));
            }
        }
    }

    float o[8][4];
    #pragma unroll
    for (int nb = 0; nb < 8; nb++)
        #pragma unroll
        for (int c = 0; c < 4; c++) o[nb][c] = 0.f;
    float mst[2] = {-1e30f, -1e30f};
    float lst[2] = {0.f, 0.f};

    for (int kt = 0; kt <= qt; kt++) {
        const int kbase = b * SEQ + kt * 64;
        __syncthreads();   // previous tile's consumers done

        // ---- producers: warp w fills records nb = w and w+4 ----
        #pragma unroll
        for (int nn = 0; nn < 2; nn++) {
            const int nb = w + nn * 4;
            #pragma unroll
            for (int kb = 0; kb < 8; kb++) {
                const uint32_t off = (uint32_t)((((kb * 8 + nb) * 64) + lane * 2) * 4);
                // K record: b0 = K[key=nb*8+gid][d=kb*8+tg], b1 = d+4
                const float* kp = g_K + (size_t)(kbase + nb * 8 + gid) * DMODEL
                                      + h * DH + kb * 8 + tg;
                float k0 = kp[0], k1 = kp[4];
                uint32_t h0 = f2tf32(k0), h1 = f2tf32(k1);
                uint32_t l0 = f2tf32(k0 - __uint_as_float(h0));
                uint32_t l1 = f2tf32(k1 - __uint_as_float(h1));
                asm volatile("st.shared.v2.b32 [%0], {%1,%2};"
                             :: "r"(Khi + off), "r"(h0), "r"(h1) : "memory");
                asm volatile("st.shared.v2.b32 [%0], {%1,%2};"
                             :: "r"(Klo + off), "r"(l0), "r"(l1) : "memory");
                // V record (V^T): b0 = V[key=kb*8+tg][d=nb*8+gid], b1 = key+4
                const float* vp = g_V + (size_t)(kbase + kb * 8 + tg) * DMODEL
                                      + h * DH + nb * 8 + gid;
                uint32_t v0 = f2tf32(vp[0]);
                uint32_t v1 = f2tf32(vp[(size_t)4 * DMODEL]);
                asm volatile("st.shared.v2.b32 [%0], {%1,%2};"
                             :: "r"(Vsm + off), "r"(v0), "r"(v1) : "memory");
            }
        }
        __syncthreads();

        // ---- S = Q K^T (3xTF32) ----
        float s[8][4];
        #pragma unroll
        for (int nb = 0; nb < 8; nb++) {
            s[nb][0] = s[nb][1] = s[nb][2] = s[nb][3] = 0.f;
            #pragma unroll
            for (int kb = 0; kb < 8; kb++) {
                const uint32_t off = (uint32_t)((((kb * 8 + nb) * 64) + lane * 2) * 4);
                uint32_t kh[2], kl[2];
                asm volatile("ld.shared.v2.b32 {%0,%1}, [%2];"
                             : "=r"(kh[0]), "=r"(kh[1]) : "r"(Khi + off));
                asm volatile("ld.shared.v2.b32 {%0,%1}, [%2];"
                             : "=r"(kl[0]), "=r"(kl[1]) : "r"(Klo + off));
                mma_tf32(s[nb], qhi[kb], kh);
                mma_tf32(s[nb], qlo[kb], kh);
                mma_tf32(s[nb], qhi[kb], kl);
            }
        }

        // ---- scale + causal mask (diagonal tile only) ----
        const bool diag = (kt == qt);
        #pragma unroll
        for (int nb = 0; nb < 8; nb++)
            #pragma unroll
            for (int c = 0; c < 4; c++) {
                s[nb][c] *= 0.125f;
                if (diag) {
                    int rl = w * 16 + gid + (c >> 1) * 8;
                    int cl = nb * 8 + 2 * tg + (c & 1);
                    if (cl > rl) s[nb][c] = -1e30f;
                }
            }

        // ---- online softmax (rows gid and gid+8; reduce across quad lanes) ----
        #pragma unroll
        for (int rh = 0; rh < 2; rh++) {
            float mx = -1e30f;
            #pragma unroll
            for (int nb = 0; nb < 8; nb++)
                mx = fmaxf(mx, fmaxf(s[nb][rh * 2], s[nb][rh * 2 + 1]));
            mx = fmaxf(mx, __shfl_xor_sync(0xffffffffu, mx, 1));
            mx = fmaxf(mx, __shfl_xor_sync(0xffffffffu, mx, 2));
            float mnew  = fmaxf(mst[rh], mx);
            float alpha = __expf(mst[rh] - mnew);
            mst[rh] = mnew;
            float sum = 0.f;
            #pragma unroll
            for (int nb = 0; nb < 8; nb++) {
                float e0 = __expf(s[nb][rh * 2]     - mnew);
                float e1 = __expf(s[nb][rh * 2 + 1] - mnew);
                s[nb][rh * 2] = e0; s[nb][rh * 2 + 1] = e1;
                sum += e0 + e1;
            }
            sum += __shfl_xor_sync(0xffffffffu, sum, 1);
            sum += __shfl_xor_sync(0xffffffffu, sum, 2);
            lst[rh] = lst[rh] * alpha + sum;
            #pragma unroll
            for (int nb = 0; nb < 8; nb++) {
                o[nb][rh * 2]     *= alpha;
                o[nb][rh * 2 + 1] *= alpha;
            }
        }

        // ---- write P (tf32 bits) to padded per-warp SMEM ----
        #pragma unroll
        for (int nb = 0; nb < 8; nb++) {
            uint32_t p0 = f2tf32(s[nb][0]), p1 = f2tf32(s[nb][1]);
            uint32_t p2 = f2tf32(s[nb][2]), p3 = f2tf32(s[nb][3]);
            uint32_t o0 = Pb + (uint32_t)(((gid)     * 68 + nb * 8 + 2 * tg) * 4);
            uint32_t o1 = Pb + (uint32_t)(((gid + 8) * 68 + nb * 8 + 2 * tg) * 4);
            asm volatile("st.shared.v2.b32 [%0], {%1,%2};"
                         :: "r"(o0), "r"(p0), "r"(p1) : "memory");
            asm volatile("st.shared.v2.b32 [%0], {%1,%2};"
                         :: "r"(o1), "r"(p2), "r"(p3) : "memory");
        }
        __syncwarp();

        // ---- O += P * V ----
        #pragma unroll
        for (int kb = 0; kb < 8; kb++) {
            uint32_t a[4];
            asm volatile("ld.shared.b32 %0, [%1];" : "=r"(a[0])
                         : "r"(Pb + (uint32_t)(((gid)     * 68 + kb * 8 + tg)     * 4)));
            asm volatile("ld.shared.b32 %0, [%1];" : "=r"(a[1])
                         : "r"(Pb + (uint32_t)(((gid + 8) * 68 + kb * 8 + tg)     * 4)));
            asm volatile("ld.shared.b32 %0, [%1];" : "=r"(a[2])
                         : "r"(Pb + (uint32_t)(((gid)     * 68 + kb * 8 + tg + 4) * 4)));
            asm volatile("ld.shared.b32 %0, [%1];" : "=r"(a[3])
                         : "r"(Pb + (uint32_t)(((gid + 8) * 68 + kb * 8 + tg + 4) * 4)));
            #pragma unroll
            for (int nb = 0; nb < 8; nb++) {
                const uint32_t off = (uint32_t)((((kb * 8 + nb) * 64) + lane * 2) * 4);
                uint32_t bf[2];
                asm volatile("ld.shared.v2.b32 {%0,%1}, [%2];"
                             : "=r"(bf[0]), "=r"(bf[1]) : "r"(Vsm + off));
                mma_tf32(o[nb], a, bf);
            }
        }
        __syncwarp();
    }

    // ---- epilogue: normalize, write g_AO ----
    #pragma unroll
    for (int rh = 0; rh < 2; rh++) {
        float inv = 1.f / lst[rh];
        int row = qbase + w * 16 + gid + rh * 8;
        float* dst = g_AO + (size_t)row * DMODEL + h * DH;
        #pragma unroll
        for (int nb = 0; nb < 8; nb++)
            *(float2*)(dst + nb * 8 + 2 * tg) =
                make_float2(o[nb][rh * 2] * inv, o[nb][rh * 2 + 1] * inv);
    }
}

// ---------------------------------------------------------------------------
// kernel_launch
// ---------------------------------------------------------------------------
extern "C" void kernel_launch(void* const* d_in, const int* in_sizes, int n_in,
                              void* d_out, int out_size)
{
    const float* X    = (const float*)d_in[0];
    const float* cosT = (const float*)d_in[1];
    const float* sinT = (const float*)d_in[2];
    const float* Wq   = (const float*)d_in[4];
    const float* Wk   = (const float*)d_in[5];
    const float* Wv   = (const float*)d_in[6];
    const float* Wo   = (const float*)d_in[7];
    float* out = (float*)d_out;

    float *pQ, *pK, *pV, *pAO;
    cudaGetSymbolAddress((void**)&pQ,  g_Q);
    cudaGetSymbolAddress((void**)&pK,  g_K);
    cudaGetSymbolAddress((void**)&pV,  g_V);
    cudaGetSymbolAddress((void**)&pAO, g_AO);

    cudaFuncSetAttribute(tgemm_kernel,
                         cudaFuncAttributeMaxDynamicSharedMemorySize, GEMM_DSMEM);
    cudaFuncSetAttribute(attn_kernel,
                         cudaFuncAttributeMaxDynamicSharedMemorySize, ATT_DSMEM);

    dim3 gemm_grid(DMODEL / 128, TROWS / 128);   // (8, 32)
    tgemm_kernel<<<gemm_grid, 256, GEMM_DSMEM>>>(X, Wq, pQ, TROWS, DMODEL, DMODEL);
    tgemm_kernel<<<gemm_grid, 256, GEMM_DSMEM>>>(X, Wk, pK, TROWS, DMODEL, DMODEL);
    tgemm_kernel<<<gemm_grid, 256, GEMM_DSMEM>>>(X, Wv, pV, TROWS, DMODEL, DMODEL);

    int rope_total = TROWS * HEADS * 32;
    rope_kernel<<<(rope_total + 255) / 256, 256>>>(cosT, sinT);

    dim3 attn_grid(SEQ / 64, HEADS, BATCH);      // (32, 16, 2)
    attn_kernel<<<attn_grid, 128, ATT_DSMEM>>>();

    tgemm_kernel<<<gemm_grid, 256, GEMM_DSMEM>>>(pAO, Wo, out, TROWS, DMODEL, DMODEL);

    (void)in_sizes; (void)n_in; (void)out_size;
}